// round 9
// baseline (speedup 1.0000x reference)
#include <cuda_runtime.h>
#include <cuda_bf16.h>

#define NN 512
#define TT 32
#define MMSG 31
#define EE 64
#define AA 64
#define NREL 201
#define NTOK (NN*TT)
#define PB 64
#define CAP 1024
#define CHUNKS 8
#define SELF_BIN (256 + 200)

// ---- device scratch ---------------------------------------------------------
__device__ float g_self[NN * EE];
__device__ float g_q[NTOK * AA];
__device__ float g_k[NTOK * AA];
__device__ float g_v[NTOK * AA];
__device__ int   g_cur[2 * 256];       // zeroed at load; re-zeroed by k_attn
__device__ int   g_list[2 * 256 * CAP];

// ---- 1. prep: zero-out + scatter (blocks 0..63) + self GEMM (64..95) ---------
__global__ __launch_bounds__(256) void k_prep(const float* __restrict__ h,
                                              const float* __restrict__ W_self,
                                              const int* __restrict__ mt,
                                              const int* __restrict__ rln,
                                              const int* __restrict__ rlm,
                                              float* __restrict__ out) {
    const int b = blockIdx.x, tid = threadIdx.x;
    if (b < 64) {
        if (tid < 128)
            ((float4*)out)[b * 128 + tid] = make_float4(0.f, 0.f, 0.f, 0.f);
        const int t = b * 256 + tid;
        const int n = t >> 5, m = t & 31;
        if (m == 0) {
            const int rqv = rln[n];
            int p0 = atomicAdd(&g_cur[rqv], 1);
            g_list[rqv * CAP + p0] = t;
            g_list[SELF_BIN * CAP + n] = t;   // deterministic slot, no atomic
        } else {
            const int i = n * MMSG + m - 1;
            const int rqv = rlm[i], rk = mt[i];
            int p0 = atomicAdd(&g_cur[rqv], 1);
            g_list[rqv * CAP + p0] = t;
            int p1 = atomicAdd(&g_cur[256 + rk], 1);
            g_list[(256 + rk) * CAP + p1] = t;
        }
        return;
    }
    if (b == 64 && tid == 0) g_cur[SELF_BIN] = NN;
    // self GEMM: register-tiled, 1 broadcast LDS + 1 LDS.128 per 4 FMA
    __shared__ float Ws[EE * EE];
    __shared__ float hb[16][EE];
    const int n0 = (b - 64) * 16;
    for (int i = tid; i < EE * EE / 4; i += 256)
        ((float4*)Ws)[i] = ((const float4*)W_self)[i];
    for (int i = tid; i < 16 * EE / 4; i += 256)
        ((float4*)&hb[0][0])[i] = ((const float4*)(h + n0 * EE))[i];
    __syncthreads();
    const int nl = tid >> 4;            // node 0..15
    const int ag = tid & 15;            // column group: cols ag*4..+3
    float acc0 = 0.f, acc1 = 0.f, acc2 = 0.f, acc3 = 0.f;
    #pragma unroll 16
    for (int e = 0; e < EE; e++) {
        const float hv = hb[nl][e];
        const float4 w = *(const float4*)(Ws + e * EE + (ag << 2));
        acc0 = fmaf(hv, w.x, acc0);
        acc1 = fmaf(hv, w.y, acc1);
        acc2 = fmaf(hv, w.z, acc2);
        acc3 = fmaf(hv, w.w, acc3);
    }
    *(float4*)(g_self + (n0 + nl) * EE + (ag << 2)) =
        make_float4(acc0, acc1, acc2, acc3);
}

// ---- 2. bucketed relation projections (proven) --------------------------------
__global__ __launch_bounds__(256) void k_proj(const float* __restrict__ msg,
                                              const float* __restrict__ Q,
                                              const float* __restrict__ K,
                                              const float* __restrict__ V) {
    const bool isK = blockIdx.x >= NREL;
    const int  r   = isK ? blockIdx.x - NREL : blockIdx.x;
    const int  bin = (isK ? 256 : 0) + r;
    const int  cnt = g_cur[bin];
    if ((int)blockIdx.y * PB >= cnt) return;

    __shared__ float Ws1[EE * AA];
    __shared__ float Ws2[EE * AA];
    __shared__ float xb[EE][PB];

    const int tid = threadIdx.x;
    const int* __restrict__ list = g_list + bin * CAP;

    {
        const float4* w1 = (const float4*)((isK ? K : Q) + (size_t)r * EE * AA);
        #pragma unroll
        for (int i = tid; i < EE * AA / 4; i += 256) ((float4*)Ws1)[i] = w1[i];
        if (!isK) {
            const float4* w2 = (const float4*)(V + (size_t)r * EE * AA);
            #pragma unroll
            for (int i = tid; i < EE * AA / 4; i += 256) ((float4*)Ws2)[i] = w2[i];
        }
    }

    const int ag = tid & 15;
    const int tg = tid >> 4;

    for (int c = blockIdx.y; c * PB < cnt; c += gridDim.y) {
        const int p  = c * PB;
        const int np = min(PB, cnt - p);
        __syncthreads();
        {
            const int tt = tid >> 2, qq = tid & 3;
            const bool valid = tt < np;
            int tok = valid ? list[p + tt] : 0;
            const int n = tok >> 5, m = tok & 31;
            const float* xp = (m == 0) ? (g_self + n * EE)
                                       : (msg + (size_t)(n * MMSG + m - 1) * EE);
            #pragma unroll
            for (int j = 0; j < 4; j++) {
                const int e = qq * 16 + j * 4;
                float4 xv = valid ? *(const float4*)(xp + e) : make_float4(0.f,0.f,0.f,0.f);
                xb[e + 0][tt] = xv.x; xb[e + 1][tt] = xv.y;
                xb[e + 2][tt] = xv.z; xb[e + 3][tt] = xv.w;
            }
        }
        __syncthreads();

        if (!isK) {
            float a1[4][4], a2[4][4];
            #pragma unroll
            for (int j = 0; j < 4; j++)
                #pragma unroll
                for (int i = 0; i < 4; i++) { a1[j][i] = 0.f; a2[j][i] = 0.f; }
            #pragma unroll 8
            for (int e = 0; e < EE; e++) {
                const float4 w1 = *(const float4*)(Ws1 + e * AA + (ag << 2));
                const float4 w2 = *(const float4*)(Ws2 + e * AA + (ag << 2));
                const float4 xt = *(const float4*)(&xb[e][tg << 2]);
                const float xv[4]  = {xt.x, xt.y, xt.z, xt.w};
                const float w1v[4] = {w1.x, w1.y, w1.z, w1.w};
                const float w2v[4] = {w2.x, w2.y, w2.z, w2.w};
                #pragma unroll
                for (int j = 0; j < 4; j++)
                    #pragma unroll
                    for (int i = 0; i < 4; i++) {
                        a1[j][i] = fmaf(xv[j], w1v[i], a1[j][i]);
                        a2[j][i] = fmaf(xv[j], w2v[i], a2[j][i]);
                    }
            }
            #pragma unroll
            for (int j = 0; j < 4; j++) {
                const int ts = (tg << 2) + j;
                if (ts < np) {
                    const int tok = list[p + ts];
                    *(float4*)(g_q + (size_t)tok * AA + (ag << 2)) =
                        make_float4(a1[j][0], a1[j][1], a1[j][2], a1[j][3]);
                    *(float4*)(g_v + (size_t)tok * AA + (ag << 2)) =
                        make_float4(a2[j][0], a2[j][1], a2[j][2], a2[j][3]);
                }
            }
        } else {
            float a1[4][4];
            #pragma unroll
            for (int j = 0; j < 4; j++)
                #pragma unroll
                for (int i = 0; i < 4; i++) a1[j][i] = 0.f;
            #pragma unroll 8
            for (int e = 0; e < EE; e++) {
                const float4 w1 = *(const float4*)(Ws1 + e * AA + (ag << 2));
                const float4 xt = *(const float4*)(&xb[e][tg << 2]);
                const float xv[4]  = {xt.x, xt.y, xt.z, xt.w};
                const float w1v[4] = {w1.x, w1.y, w1.z, w1.w};
                #pragma unroll
                for (int j = 0; j < 4; j++)
                    #pragma unroll
                    for (int i = 0; i < 4; i++)
                        a1[j][i] = fmaf(xv[j], w1v[i], a1[j][i]);
            }
            #pragma unroll
            for (int j = 0; j < 4; j++) {
                const int ts = (tg << 2) + j;
                if (ts < np) {
                    const int tok = list[p + ts];
                    *(float4*)(g_k + (size_t)tok * AA + (ag << 2)) =
                        make_float4(a1[j][0], a1[j][1], a1[j][2], a1[j][3]);
                }
            }
        }
    }
}

// ---- 3. attention split: 2 CTAs per node, all 256 threads in every phase ------
#define KHALF 16
#define QST 68
#define KTST 18
struct __align__(16) Attn2Smem {
    float qs[TT * QST];
    float vs[KHALF * QST];
    float kT[EE * KTST];
    float sc[TT][KHALF + 1];
    float att0[KHALF];
    float ppart[4][AA];   // pooled partials
    float pooled[AA];
    float fpart[4][EE];   // ffn partials
};
__global__ __launch_bounds__(256) void k_attn(const float* __restrict__ ffn_w,
                                              const float* __restrict__ ffn_b,
                                              float* __restrict__ out) {
    const int n = blockIdx.x, half = blockIdx.y, tid = threadIdx.x;
    if (n == 0 && half == 0) { g_cur[tid] = 0; g_cur[256 + tid] = 0; }
    __shared__ Attn2Smem s;

    const float4* gq = (const float4*)(g_q + (size_t)n * TT * AA);
    const float4* gk = (const float4*)(g_k + (size_t)n * TT * AA + (size_t)half * KHALF * AA);
    const float4* gv = (const float4*)(g_v + (size_t)n * TT * AA + (size_t)half * KHALF * AA);

    const int i1 = tid + 256;
    const float4 q0 = gq[tid], q1 = gq[i1];
    const float4 k0 = gk[tid];
    const float4 v0 = gv[tid];
    {
        const int r0 = tid >> 4, c0 = (tid & 15) << 2;
        const int r1 = i1 >> 4, c1 = (i1 & 15) << 2;
        *(float4*)(s.qs + r0 * QST + c0) = q0;
        *(float4*)(s.qs + r1 * QST + c1) = q1;
        *(float4*)(s.vs + r0 * QST + c0) = v0;
        s.kT[(c0 + 0) * KTST + r0] = k0.x;
        s.kT[(c0 + 1) * KTST + r0] = k0.y;
        s.kT[(c0 + 2) * KTST + r0] = k0.z;
        s.kT[(c0 + 3) * KTST + r0] = k0.w;
    }
    __syncthreads();

    // scores: thread -> q-row x 2 k-cols (kT reads broadcast across qr groups)
    {
        const int qr = tid >> 3, kc0 = (tid & 7) << 1;
        float a0 = 0.f, a1 = 0.f;
        #pragma unroll 16
        for (int e = 0; e < EE; e++) {
            const float qv = s.qs[qr * QST + e];
            const float2 k2 = *(const float2*)(s.kT + e * KTST + kc0);
            a0 = fmaf(qv, k2.x, a0);
            a1 = fmaf(qv, k2.y, a1);
        }
        s.sc[qr][kc0 + 0] = a0 * 0.125f;
        s.sc[qr][kc0 + 1] = a1 * 0.125f;
    }
    __syncthreads();

    // column softmax over 32 query rows (only 16 columns here)
    if (tid < KHALF) {
        const int kc = tid;
        float mx = -1e30f;
        #pragma unroll
        for (int q = 0; q < TT; q++) mx = fmaxf(mx, s.sc[q][kc]);
        float sum = 0.f;
        #pragma unroll
        for (int q = 0; q < TT; q++) sum += __expf(s.sc[q][kc] - mx);
        s.att0[kc] = __expf(s.sc[0][kc] - mx) / sum;
    }
    __syncthreads();

    // pooled partials: 256 threads = 64 cols x 4 k-groups (4 k each)
    {
        const int a = tid & 63, grp = tid >> 6;
        float acc = 0.f;
        #pragma unroll
        for (int k = 0; k < 4; k++) {
            const int kk = grp * 4 + k;
            acc = fmaf(s.att0[kk], s.vs[kk * QST + a], acc);
        }
        s.ppart[grp][a] = acc;
    }
    __syncthreads();
    if (tid < AA)
        s.pooled[tid] = s.ppart[0][tid] + s.ppart[1][tid]
                      + s.ppart[2][tid] + s.ppart[3][tid];
    __syncthreads();

    // FFN partials: 256 threads = 64 outputs x 4 a-groups (16 a each)
    {
        const int o = tid & 63, grp = tid >> 6;
        float acc = 0.f;
        #pragma unroll
        for (int a = 0; a < 16; a++) {
            const int aa = grp * 16 + a;
            acc = fmaf(s.pooled[aa], ffn_w[aa * EE + o], acc);
        }
        s.fpart[grp][o] = acc;
    }
    __syncthreads();
    if (tid < EE) {
        float acc = s.fpart[0][tid] + s.fpart[1][tid]
                  + s.fpart[2][tid] + s.fpart[3][tid];
        if (half == 0) acc += ffn_b[tid];
        atomicAdd(&out[n * EE + tid], acc);
    }
}

extern "C" void kernel_launch(void* const* d_in, const int* in_sizes, int n_in,
                              void* d_out, int out_size) {
    const float* h            = (const float*)d_in[0];
    const float* msg          = (const float*)d_in[1];
    const int*   msg_type     = (const int*)  d_in[2];
    const int*   r_label_node = (const int*)  d_in[3];
    const int*   r_label_msg  = (const int*)  d_in[4];
    const float* W_self       = (const float*)d_in[5];
    const float* Q            = (const float*)d_in[6];
    const float* K            = (const float*)d_in[7];
    const float* V            = (const float*)d_in[8];
    const float* ffn_w        = (const float*)d_in[9];
    const float* ffn_b        = (const float*)d_in[10];
    float* out = (float*)d_out;

    k_prep<<<96, 256>>>(h, W_self, msg_type, r_label_node, r_label_msg, out);
    dim3 pg(2 * NREL, CHUNKS);
    k_proj<<<pg, 256>>>(msg, Q, K, V);
    dim3 ag(NN, 2);
    k_attn<<<ag, 256>>>(ffn_w, ffn_b, out);
}